// round 6
// baseline (speedup 1.0000x reference)
#include <cuda_runtime.h>
#include <math.h>

#define B_ 2
#define S_ 2048
#define D_ 1024
#define H_ 16
#define HD_ 64

// ---------------- scratch ----------------
__device__ float g_ada[B_ * 6 * D_];
__device__ float g_h[(size_t)B_ * S_ * D_];
__device__ float g_qkv[(size_t)B_ * S_ * 3 * D_];
__device__ float g_attn2[(size_t)B_ * S_ * D_];
__device__ float g_x1[(size_t)B_ * S_ * D_];
__device__ float g_mlp[(size_t)B_ * S_ * 4 * D_];
// pre-rounded weights
__device__ float g_wqkv[(size_t)3 * D_ * D_];
__device__ float g_wout[(size_t)D_ * D_];
__device__ float g_w1[(size_t)4 * D_ * D_];
__device__ float g_w2[(size_t)4 * D_ * D_];

__device__ __forceinline__ unsigned f2tf(float f) {
    unsigned u;
    asm("cvt.rna.tf32.f32 %0, %1;" : "=r"(u) : "f"(f));
    return u;
}
// emulate RN for tf32: HW truncates low 13 bits, so +0x1000 = RN(ties up)
__device__ __forceinline__ float rndf(float v) {
    return __uint_as_float(__float_as_uint(v) + 0x1000u);
}

__device__ __forceinline__ float gelu_tanh(float v) {
    float u = 0.7978845608028654f * (v + 0.044715f * v * v * v);
    return 0.5f * v * (1.f + tanhf(u));
}

__device__ __forceinline__ void cp16(void* s, const void* g) {
    unsigned sa = (unsigned)__cvta_generic_to_shared(s);
    asm volatile("cp.async.cg.shared.global [%0], [%1], 16;" :: "r"(sa), "l"(g));
}
#define CP_COMMIT() asm volatile("cp.async.commit_group;")
#define CP_WAIT(n)  asm volatile("cp.async.wait_group %0;" :: "n"(n))

// ---------------- pre-round weights (tf32 RN at rest) ----------------
__global__ void round_weights(const float* __restrict__ src, float* __restrict__ dst, int n4)
{
    int i = blockIdx.x * 256 + threadIdx.x;
    if (i >= n4) return;
    float4 v = reinterpret_cast<const float4*>(src)[i];
    v.x = rndf(v.x); v.y = rndf(v.y); v.z = rndf(v.z); v.w = rndf(v.w);
    reinterpret_cast<float4*>(dst)[i] = v;
}

// ============================================================================
// Fused flash attention. Inputs in qkv are pre-rounded tf32 bits, Q pre-scaled
// by 1/8 (done in the QKV GEMM epilogue). No per-fragment rounding needed.
// 512 threads = 16 warps, Q tile 256 rows, key tiles of 64.
// ============================================================================
#define FA_SMEM 210944

__global__ void __launch_bounds__(512) flash_attn(
    const float* __restrict__ qkv, float* __restrict__ out)
{
    extern __shared__ unsigned sm[];
    unsigned* Qs  = sm;                     // [256][68]
    unsigned* Ks  = sm + 17408;             // [2][64][68]
    unsigned* Vs  = sm + 26112;             // [2][64][72]
    unsigned* Psw = sm + 35328;             // 16 x [16][68]

    const int tid  = threadIdx.x;
    const int lane = tid & 31;
    const int warp = tid >> 5;
    const int grp  = lane >> 2;
    const int tig  = lane & 3;
    const int b    = blockIdx.y >> 4;
    const int h    = blockIdx.y & 15;
    const int qBase = blockIdx.x * 256;

#pragma unroll
    for (int i = 0; i < 8; i++) {
        int idx = tid + i * 512;
        int r   = idx >> 4;
        int qd  = idx & 15;
        cp16(&Qs[r * 68 + qd * 4],
             &qkv[((long)(b * S_ + qBase + r)) * 3072 + h * 64 + qd * 4]);
    }
#pragma unroll
    for (int i = 0; i < 2; i++) {
        int idx = tid + i * 512;
        int r   = idx >> 4;
        int qd  = idx & 15;
        const float* base = &qkv[((long)(b * S_ + r)) * 3072 + h * 64 + qd * 4];
        cp16(&Ks[r * 68 + qd * 4], base + 1024);
        cp16(&Vs[r * 72 + qd * 4], base + 2048);
    }
    CP_COMMIT();

    unsigned* Ps = Psw + warp * 16 * 68;
    const unsigned* Qw = Qs + warp * 16 * 68;

    float m0 = -INFINITY, m1 = -INFINITY, l0 = 0.f, l1 = 0.f;
    float o[8][4];
#pragma unroll
    for (int j = 0; j < 8; j++)
#pragma unroll
        for (int t = 0; t < 4; t++) o[j][t] = 0.f;

    const int nT = S_ / 64;
    for (int t = 0; t < nT; t++) {
        CP_WAIT(0);
        __syncthreads();

        if (t + 1 < nT) {
            unsigned* Kn = Ks + ((t + 1) & 1) * 4352;
            unsigned* Vn = Vs + ((t + 1) & 1) * 4608;
            int kt = (t + 1) * 64;
#pragma unroll
            for (int i = 0; i < 2; i++) {
                int idx = tid + i * 512;
                int r   = idx >> 4;
                int qd  = idx & 15;
                const float* base = &qkv[((long)(b * S_ + kt + r)) * 3072 + h * 64 + qd * 4];
                cp16(&Kn[r * 68 + qd * 4], base + 1024);
                cp16(&Vn[r * 72 + qd * 4], base + 2048);
            }
        }
        CP_COMMIT();

        const unsigned* Kc = Ks + (t & 1) * 4352;
        const unsigned* Vc = Vs + (t & 1) * 4608;

        // ---- scores = Q @ K^T (Q pre-scaled by 1/8) ----
        float s[8][4];
#pragma unroll
        for (int j = 0; j < 8; j++)
#pragma unroll
            for (int tt = 0; tt < 4; tt++) s[j][tt] = 0.f;

#pragma unroll
        for (int kk = 0; kk < 64; kk += 8) {
            unsigned a0 = Qw[grp * 68 + kk + tig];
            unsigned a1 = Qw[(grp + 8) * 68 + kk + tig];
            unsigned a2 = Qw[grp * 68 + kk + tig + 4];
            unsigned a3 = Qw[(grp + 8) * 68 + kk + tig + 4];
#pragma unroll
            for (int j = 0; j < 8; j++) {
                unsigned b0 = Kc[(j * 8 + grp) * 68 + kk + tig];
                unsigned b1 = Kc[(j * 8 + grp) * 68 + kk + tig + 4];
                asm volatile(
                    "mma.sync.aligned.m16n8k8.row.col.f32.tf32.tf32.f32 "
                    "{%0,%1,%2,%3}, {%4,%5,%6,%7}, {%8,%9}, {%0,%1,%2,%3};"
                    : "+f"(s[j][0]), "+f"(s[j][1]), "+f"(s[j][2]), "+f"(s[j][3])
                    : "r"(a0), "r"(a1), "r"(a2), "r"(a3), "r"(b0), "r"(b1));
            }
        }

        // ---- online softmax ----
        float mx0 = -INFINITY, mx1 = -INFINITY;
#pragma unroll
        for (int j = 0; j < 8; j++) {
            mx0 = fmaxf(mx0, fmaxf(s[j][0], s[j][1]));
            mx1 = fmaxf(mx1, fmaxf(s[j][2], s[j][3]));
        }
        mx0 = fmaxf(mx0, __shfl_xor_sync(0xffffffffu, mx0, 1));
        mx0 = fmaxf(mx0, __shfl_xor_sync(0xffffffffu, mx0, 2));
        mx1 = fmaxf(mx1, __shfl_xor_sync(0xffffffffu, mx1, 1));
        mx1 = fmaxf(mx1, __shfl_xor_sync(0xffffffffu, mx1, 2));
        float mn0 = fmaxf(m0, mx0), mn1 = fmaxf(m1, mx1);
        float sc0 = __expf(m0 - mn0), sc1 = __expf(m1 - mn1);

        float sum0 = 0.f, sum1 = 0.f;
#pragma unroll
        for (int j = 0; j < 8; j++) {
            float p0 = __expf(s[j][0] - mn0);
            float p1 = __expf(s[j][1] - mn0);
            float p2 = __expf(s[j][2] - mn1);
            float p3 = __expf(s[j][3] - mn1);
            sum0 += p0 + p1; sum1 += p2 + p3;
            Ps[grp * 68 + j * 8 + tig * 2]           = f2tf(p0);
            Ps[grp * 68 + j * 8 + tig * 2 + 1]       = f2tf(p1);
            Ps[(grp + 8) * 68 + j * 8 + tig * 2]     = f2tf(p2);
            Ps[(grp + 8) * 68 + j * 8 + tig * 2 + 1] = f2tf(p3);
        }
        sum0 += __shfl_xor_sync(0xffffffffu, sum0, 1);
        sum0 += __shfl_xor_sync(0xffffffffu, sum0, 2);
        sum1 += __shfl_xor_sync(0xffffffffu, sum1, 1);
        sum1 += __shfl_xor_sync(0xffffffffu, sum1, 2);
        l0 = l0 * sc0 + sum0;
        l1 = l1 * sc1 + sum1;
        m0 = mn0; m1 = mn1;

#pragma unroll
        for (int j = 0; j < 8; j++) {
            o[j][0] *= sc0; o[j][1] *= sc0;
            o[j][2] *= sc1; o[j][3] *= sc1;
        }
        __syncwarp();

        // ---- O += P @ V ----
#pragma unroll
        for (int kk = 0; kk < 64; kk += 8) {
            unsigned a0 = Ps[grp * 68 + kk + tig];
            unsigned a1 = Ps[(grp + 8) * 68 + kk + tig];
            unsigned a2 = Ps[grp * 68 + kk + tig + 4];
            unsigned a3 = Ps[(grp + 8) * 68 + kk + tig + 4];
#pragma unroll
            for (int j = 0; j < 8; j++) {
                unsigned b0 = Vc[(kk + tig) * 72 + j * 8 + grp];
                unsigned b1 = Vc[(kk + tig + 4) * 72 + j * 8 + grp];
                asm volatile(
                    "mma.sync.aligned.m16n8k8.row.col.f32.tf32.tf32.f32 "
                    "{%0,%1,%2,%3}, {%4,%5,%6,%7}, {%8,%9}, {%0,%1,%2,%3};"
                    : "+f"(o[j][0]), "+f"(o[j][1]), "+f"(o[j][2]), "+f"(o[j][3])
                    : "r"(a0), "r"(a1), "r"(a2), "r"(a3), "r"(b0), "r"(b1));
            }
        }
        __syncwarp();
    }

    // ---- normalize + store (pre-rounded for downstream out-proj GEMM) ----
    float inv0 = 1.f / l0, inv1 = 1.f / l1;
    int row0 = qBase + warp * 16 + grp;
#pragma unroll
    for (int j = 0; j < 8; j++) {
        int col = h * 64 + j * 8 + tig * 2;
        float2 v0 = make_float2(rndf(o[j][0] * inv0), rndf(o[j][1] * inv0));
        *reinterpret_cast<float2*>(&out[((long)(b * S_ + row0)) * D_ + col]) = v0;
        float2 v1 = make_float2(rndf(o[j][2] * inv1), rndf(o[j][3] * inv1));
        *reinterpret_cast<float2*>(&out[((long)(b * S_ + row0 + 8)) * D_ + col]) = v1;
    }
}

// ============================================================================
// TF32 tensor-core NT GEMM, 3-stage cp.async pipeline, fused epilogues.
// Inputs A and B must be PRE-ROUNDED (tf32 RN bits in fp32 storage).
// mode 0: plain       mode 1: rnd(gelu(v + evec[col]))
// mode 2: EX + ada*v  mode 3: EX + ada*(v + evec)
// mode 4: qkv: v *= (col<1024 ? 0.125 : 1), then rnd   (Q pre-scale + round)
// ============================================================================
#define GSTAGES 3
#define GEMM_SMEM (GSTAGES * 128 * 20 * 4 * 2)   // 61440 B

__global__ void __launch_bounds__(256) gemm_nt_tf32(
    const float* __restrict__ A, const float* __restrict__ B, float* __restrict__ C,
    int N, int K, int lda, int ldb, int ldc,
    int mode, const float* __restrict__ EX, const float* __restrict__ evec,
    const float* __restrict__ ada, int adaOff)
{
    extern __shared__ unsigned gsm[];
    unsigned* Asm = gsm;                         // [GSTAGES][128][20]
    unsigned* Bsm = gsm + GSTAGES * 128 * 20;

    const int tid   = threadIdx.x;
    const int lane  = tid & 31;
    const int warp  = tid >> 5;
    const int warpM = warp & 1;
    const int warpN = warp >> 1;
    const int grp   = lane >> 2;
    const int tig   = lane & 3;

    const int rowBase = blockIdx.y * 128;
    const int colBase = blockIdx.x * 128;

    const int rowA = tid >> 2;
    const int quad = tid & 3;
    const float* aBase = A + (long)(rowBase + rowA) * lda + quad * 4;
    const float* bBase = B + (long)(colBase + rowA) * ldb + quad * 4;

    float acc[4][4][4];
#pragma unroll
    for (int i = 0; i < 4; i++)
#pragma unroll
        for (int j = 0; j < 4; j++)
#pragma unroll
            for (int t = 0; t < 4; t++) acc[i][j][t] = 0.f;

    const int nCh = K >> 4;

    auto load_chunk = [&](int c, int st) {
        const float* ap = aBase + c * 16;
        const float* bp = bBase + c * 16;
        unsigned* as = Asm + st * 128 * 20;
        unsigned* bs = Bsm + st * 128 * 20;
        cp16(&as[rowA * 20 + quad * 4], ap);
        cp16(&as[(rowA + 64) * 20 + quad * 4], ap + (long)64 * lda);
        cp16(&bs[rowA * 20 + quad * 4], bp);
        cp16(&bs[(rowA + 64) * 20 + quad * 4], bp + (long)64 * ldb);
    };

#pragma unroll
    for (int s = 0; s < GSTAGES - 1; s++) {
        if (s < nCh) load_chunk(s, s);
        CP_COMMIT();
    }

    int st = 0;
    for (int c = 0; c < nCh; c++) {
        CP_WAIT(GSTAGES - 2);
        __syncthreads();

        int nc = c + GSTAGES - 1;
        if (nc < nCh) load_chunk(nc, nc % GSTAGES);
        CP_COMMIT();

        const unsigned* as = Asm + st * 128 * 20;
        const unsigned* bs = Bsm + st * 128 * 20;
#pragma unroll
        for (int kb = 0; kb < 2; kb++) {
            const int kk = kb * 8;
            unsigned af[4][4], bfr[4][2];
#pragma unroll
            for (int i = 0; i < 4; i++) {
                int r0 = warpM * 64 + i * 16 + grp;
                af[i][0] = as[r0 * 20 + kk + tig];
                af[i][1] = as[(r0 + 8) * 20 + kk + tig];
                af[i][2] = as[r0 * 20 + kk + tig + 4];
                af[i][3] = as[(r0 + 8) * 20 + kk + tig + 4];
            }
#pragma unroll
            for (int j = 0; j < 4; j++) {
                int c0 = warpN * 32 + j * 8 + grp;
                bfr[j][0] = bs[c0 * 20 + kk + tig];
                bfr[j][1] = bs[c0 * 20 + kk + tig + 4];
            }
#pragma unroll
            for (int i = 0; i < 4; i++)
#pragma unroll
                for (int j = 0; j < 4; j++) {
                    asm volatile(
                        "mma.sync.aligned.m16n8k8.row.col.f32.tf32.tf32.f32 "
                        "{%0,%1,%2,%3}, {%4,%5,%6,%7}, {%8,%9}, {%0,%1,%2,%3};"
                        : "+f"(acc[i][j][0]), "+f"(acc[i][j][1]),
                          "+f"(acc[i][j][2]), "+f"(acc[i][j][3])
                        : "r"(af[i][0]), "r"(af[i][1]), "r"(af[i][2]), "r"(af[i][3]),
                          "r"(bfr[j][0]), "r"(bfr[j][1]));
                }
        }
        st = (st + 1 == GSTAGES) ? 0 : st + 1;
    }

    // ---- epilogue ----
#pragma unroll
    for (int i = 0; i < 4; i++) {
#pragma unroll
        for (int j = 0; j < 4; j++) {
            long row = rowBase + warpM * 64 + i * 16 + grp;
            int col = colBase + warpN * 32 + j * 8 + tig * 2;
#pragma unroll
            for (int half = 0; half < 2; half++) {
                long r = row + half * 8;
                float v0 = acc[i][j][half * 2];
                float v1 = acc[i][j][half * 2 + 1];
                if (mode == 4) {
                    float qs = (col < 1024) ? 0.125f : 1.f;
                    v0 = rndf(v0 * qs);
                    v1 = rndf(v1 * qs);
                } else if (mode == 1) {
                    v0 = rndf(gelu_tanh(v0 + evec[col]));
                    v1 = rndf(gelu_tanh(v1 + evec[col + 1]));
                } else if (mode == 2) {
                    int bb = (int)(r >> 11);
                    v0 = EX[r * ldc + col] + ada[bb * 6 * D_ + adaOff + col] * v0;
                    v1 = EX[r * ldc + col + 1] + ada[bb * 6 * D_ + adaOff + col + 1] * v1;
                } else if (mode == 3) {
                    int bb = (int)(r >> 11);
                    v0 = EX[r * ldc + col] + ada[bb * 6 * D_ + adaOff + col] * (v0 + evec[col]);
                    v1 = EX[r * ldc + col + 1] + ada[bb * 6 * D_ + adaOff + col + 1] * (v1 + evec[col + 1]);
                }
                *reinterpret_cast<float2*>(&C[r * ldc + col]) = make_float2(v0, v1);
            }
        }
    }
}

// ---------------- adaLN ----------------
__global__ void __launch_bounds__(256) ada_kernel(
    const float* __restrict__ c, const float* __restrict__ w,
    const float* __restrict__ bias, float* __restrict__ out)
{
    int warp = (blockIdx.x * blockDim.x + threadIdx.x) >> 5;
    int lane = threadIdx.x & 31;
    if (warp >= 6 * D_) return;
    const float* wr = w + (long)warp * D_;
    float s0 = 0.f, s1 = 0.f;
    for (int d = lane; d < D_; d += 32) {
        float wv = wr[d];
        s0 += c[d] * wv;
        s1 += c[D_ + d] * wv;
    }
#pragma unroll
    for (int o = 16; o > 0; o >>= 1) {
        s0 += __shfl_down_sync(0xffffffffu, s0, o);
        s1 += __shfl_down_sync(0xffffffffu, s1, o);
    }
    if (lane == 0) {
        out[warp] = s0 + bias[warp];
        out[6 * D_ + warp] = s1 + bias[warp];
    }
}

// ---------------- LayerNorm + modulate (pre-rounded output) ----------------
__global__ void __launch_bounds__(256) ln_mod_kernel(
    const float* __restrict__ x, const float* __restrict__ w,
    const float* __restrict__ ada, int shOff, int scOff, float* __restrict__ h)
{
    int r = blockIdx.x;
    int b = r >> 11;
    const float* xr = x + (long)r * D_;
    int tid = threadIdx.x;
    float s = 0.f, ss = 0.f;
    float vals[4];
#pragma unroll
    for (int i = 0; i < 4; i++) {
        float v = xr[tid + i * 256];
        vals[i] = v; s += v; ss += v * v;
    }
    __shared__ float rs[256], rss[256];
    rs[tid] = s; rss[tid] = ss;
    __syncthreads();
    for (int st = 128; st > 0; st >>= 1) {
        if (tid < st) { rs[tid] += rs[tid + st]; rss[tid] += rss[tid + st]; }
        __syncthreads();
    }
    float mean = rs[0] * (1.f / D_);
    float var = rss[0] * (1.f / D_) - mean * mean;
    float inv = rsqrtf(var + 1e-5f);
    const float* sh = ada + b * 6 * D_ + shOff;
    const float* sc = ada + b * 6 * D_ + scOff;
#pragma unroll
    for (int i = 0; i < 4; i++) {
        int d = tid + i * 256;
        h[(long)r * D_ + d] = rndf((vals[i] - mean) * inv * w[d] * (1.f + sc[d]) + sh[d]);
    }
}

// ---------------- launch ----------------
extern "C" void kernel_launch(void* const* d_in, const int* in_sizes, int n_in,
                              void* d_out, int out_size)
{
    (void)in_sizes; (void)n_in; (void)out_size;
    const float* x       = (const float*)d_in[0];
    const float* c       = (const float*)d_in[3];
    const float* norm1_w = (const float*)d_in[4];
    const float* w_qkv   = (const float*)d_in[5];
    const float* w_out   = (const float*)d_in[6];
    const float* norm2_w = (const float*)d_in[7];
    const float* mlp_w1  = (const float*)d_in[8];
    const float* mlp_b1  = (const float*)d_in[9];
    const float* mlp_w2  = (const float*)d_in[10];
    const float* mlp_b2  = (const float*)d_in[11];
    const float* ada_w   = (const float*)d_in[12];
    const float* ada_b   = (const float*)d_in[13];
    float* out = (float*)d_out;

    float *ada, *h, *qkv, *attn2, *x1, *mlp, *wqkv_r, *wout_r, *w1_r, *w2_r;
    cudaGetSymbolAddress((void**)&ada,    g_ada);
    cudaGetSymbolAddress((void**)&h,      g_h);
    cudaGetSymbolAddress((void**)&qkv,    g_qkv);
    cudaGetSymbolAddress((void**)&attn2,  g_attn2);
    cudaGetSymbolAddress((void**)&x1,     g_x1);
    cudaGetSymbolAddress((void**)&mlp,    g_mlp);
    cudaGetSymbolAddress((void**)&wqkv_r, g_wqkv);
    cudaGetSymbolAddress((void**)&wout_r, g_wout);
    cudaGetSymbolAddress((void**)&w1_r,   g_w1);
    cudaGetSymbolAddress((void**)&w2_r,   g_w2);

    static int inited = 0;
    if (!inited) {
        cudaFuncSetAttribute(flash_attn, cudaFuncAttributeMaxDynamicSharedMemorySize, FA_SMEM);
        cudaFuncSetAttribute(gemm_nt_tf32, cudaFuncAttributeMaxDynamicSharedMemorySize, GEMM_SMEM);
        inited = 1;
    }

    // 0. pre-round weights for tf32 RN
    round_weights<<<(3 * D_ * D_ / 4 + 255) / 256, 256>>>(w_qkv, wqkv_r, 3 * D_ * D_ / 4);
    round_weights<<<(D_ * D_ / 4 + 255) / 256, 256>>>(w_out, wout_r, D_ * D_ / 4);
    round_weights<<<(4 * D_ * D_ / 4 + 255) / 256, 256>>>(mlp_w1, w1_r, 4 * D_ * D_ / 4);
    round_weights<<<(4 * D_ * D_ / 4 + 255) / 256, 256>>>(mlp_w2, w2_r, 4 * D_ * D_ / 4);
    // 1. adaLN projection
    ada_kernel<<<768, 256>>>(c, ada_w, ada_b, ada);
    // 2. LN1 + modulate (rounded)
    ln_mod_kernel<<<B_ * S_, 256>>>(x, norm1_w, ada, 0, D_, h);
    // 3. QKV GEMM (epilogue: scale Q by 1/8, round all)
    gemm_nt_tf32<<<dim3(24, 32), 256, GEMM_SMEM>>>(h, wqkv_r, qkv, 3 * D_, D_,
                                                   D_, D_, 3 * D_, 4,
                                                   nullptr, nullptr, nullptr, 0);
    // 4. flash attention -> attn2 (rounded)
    flash_attn<<<dim3(S_ / 256, B_ * H_), 512, FA_SMEM>>>(qkv, attn2);
    // 5. out-proj + residual1
    gemm_nt_tf32<<<dim3(8, 32), 256, GEMM_SMEM>>>(attn2, wout_r, x1, D_, D_,
                                                  D_, D_, D_, 2,
                                                  x, nullptr, ada, 2 * D_);
    // 6. LN2 + modulate (rounded)
    ln_mod_kernel<<<B_ * S_, 256>>>(x1, norm2_w, ada, 3 * D_, 4 * D_, h);
    // 7. MLP1 + bias + gelu (rounded)
    gemm_nt_tf32<<<dim3(32, 32), 256, GEMM_SMEM>>>(h, w1_r, mlp, 4 * D_, D_,
                                                   D_, D_, 4 * D_, 1,
                                                   nullptr, mlp_b1, nullptr, 0);
    // 8. MLP2 + final residual
    gemm_nt_tf32<<<dim3(8, 32), 256, GEMM_SMEM>>>(mlp, w2_r, out, D_, 4 * D_,
                                                  4 * D_, 4 * D_, D_, 3,
                                                  x1, mlp_b2, ada, 5 * D_);
}